// round 16
// baseline (speedup 1.0000x reference)
#include <cuda_runtime.h>
#include <cuda_fp16.h>
#include <cstdint>

#define N_NODES 100000
#define N_EDGES 640000
#define E_PAD 1048576   // >= sum of pad4(deg)
#define D 128
#define SCAN_BS 1024
#define N_SCAN_BLOCKS ((N_NODES + SCAN_BS - 1) / SCAN_BS)  // 98
#define M_TILE 64
#define GEMM_BLOCKS ((N_NODES + M_TILE - 1) / M_TILE)      // 1563

// ---- scratch ----
__device__ __half g_h[(size_t)N_NODES * D];
__device__ __half g_h2[(size_t)N_NODES * D];
// pre-swizzled fp16 A-tile images: [tile][64 rows][256B] = 16KB/tile
__device__ unsigned char g_ahi[(size_t)GEMM_BLOCKS * 16384];
__device__ int   g_deg[N_NODES];
__device__ float g_dinv[N_NODES];
__device__ int   g_rowptr[N_NODES + 1];
__device__ int   g_cursor[N_NODES];
__device__ int   g_bsum[128];
__device__ int   g_boff[128];
__device__ int   g_esrc[E_PAD];
__device__ float g_enorm[E_PAD];
__device__ int   g_ei[2 * N_EDGES];
// W transposed, fp16 hi/lo split, pre-swizzled: [layer][hi|lo] 32KB each
__device__ unsigned char g_wt[3 * 2 * 32768];

__device__ __forceinline__ uint32_t swz(int row, int kb) {
    return (uint32_t)(row * 256 + (kb ^ ((row & 7) << 4)));
}

__device__ __forceinline__ uint32_t s2u(const void* p) {
    uint32_t a;
    asm("{ .reg .u64 t; cvta.to.shared.u64 t, %1; cvt.u32.u64 %0, t; }"
        : "=r"(a) : "l"(p));
    return a;
}

#define LDSM_X4(d, a) \
    asm volatile("ldmatrix.sync.aligned.m8n8.x4.shared.b16 {%0,%1,%2,%3}, [%4];" \
        : "=r"((d)[0]), "=r"((d)[1]), "=r"((d)[2]), "=r"((d)[3]) : "r"(a))

#define MMA_F16(c, a, b0, b1) \
    asm volatile("mma.sync.aligned.m16n8k16.row.col.f32.f16.f16.f32 " \
        "{%0,%1,%2,%3}, {%4,%5,%6,%7}, {%8,%9}, {%0,%1,%2,%3};" \
        : "+f"((c)[0]), "+f"((c)[1]), "+f"((c)[2]), "+f"((c)[3]) \
        : "r"((a)[0]), "r"((a)[1]), "r"((a)[2]), "r"((a)[3]), "r"(b0), "r"(b1))

#define CP_ASYNC16(dst, src) \
    asm volatile("cp.async.ca.shared.global [%0], [%1], 16;" :: "r"(dst), "l"(src))
#define CP_COMMIT() asm volatile("cp.async.commit_group;")
#define CP_WAIT0()  asm volatile("cp.async.wait_group 0;")

__device__ __forceinline__ int pad4(int d) { return (d + 3) & ~3; }

// ---------------- edge-index dtype sniff ----------------
__device__ __forceinline__ bool ei_is_int64(const int* __restrict__ w) {
    bool z = true;
#pragma unroll
    for (int i = 1; i < 32; i += 2) z &= (w[i] == 0);
    return z;
}

__global__ void k_convert_hist(const int* __restrict__ ei_raw, int* __restrict__ ei32,
                               int* __restrict__ deg) {
    int e = blockIdx.x * blockDim.x + threadIdx.x;
    if (e >= N_EDGES) return;
    bool is64 = ei_is_int64(ei_raw);
    int r = is64 ? ei_raw[2 * e] : ei_raw[e];
    int c = is64 ? ei_raw[2 * (N_EDGES + e)] : ei_raw[N_EDGES + e];
    ei32[e] = r;
    ei32[N_EDGES + e] = c;
    atomicAdd(&deg[c], 1);
}

// ---------------- W prep: transpose + fp16 hi/lo split + swizzle ----------------
__global__ void k_wprep(const float* __restrict__ W) {
    int i = blockIdx.x * blockDim.x + threadIdx.x;
    if (i >= 3 * 128 * 128) return;
    int l = i >> 14;
    int rem = i & 16383;
    int k = rem >> 7;
    int n = rem & 127;
    float w = W[l * 16384 + k * 128 + n];
    __half hb = __float2half_rn(w);
    __half lb = __float2half_rn(w - __half2float(hb));
    uint32_t pos = swz(n, k * 2);
    *(__half*)(g_wt + (size_t)(l * 2 + 0) * 32768 + pos) = hb;
    *(__half*)(g_wt + (size_t)(l * 2 + 1) * 32768 + pos) = lb;
}

// ---------------- prep (padded CSR, pad4) ----------------
__global__ __launch_bounds__(256) void k_dinv_bsum(const int* __restrict__ deg,
                                                   float* __restrict__ dinv,
                                                   int* __restrict__ bsum) {
    __shared__ int s[256];
    int b = blockIdx.x, t = threadIdx.x;
    int base = b * SCAN_BS + t * 4;
    int v = 0;
#pragma unroll
    for (int j = 0; j < 4; j++) {
        int i = base + j;
        if (i < N_NODES) {
            int d = deg[i];
            dinv[i] = (d > 0) ? rsqrtf((float)d) : 0.f;
            v += pad4(d);
        }
    }
    s[t] = v;
    __syncthreads();
    for (int off = 128; off > 0; off >>= 1) {
        if (t < off) s[t] += s[t + off];
        __syncthreads();
    }
    if (t == 0) bsum[b] = s[0];
}

__global__ __launch_bounds__(128) void k_scansums(const int* __restrict__ bsum,
                                                  int* __restrict__ boff,
                                                  int* __restrict__ rowptr) {
    __shared__ int s[128];
    int t = threadIdx.x;
    int v = (t < N_SCAN_BLOCKS) ? bsum[t] : 0;
    s[t] = v;
    __syncthreads();
    for (int off = 1; off < 128; off <<= 1) {
        int u = (t >= off) ? s[t - off] : 0;
        __syncthreads();
        s[t] += u;
        __syncthreads();
    }
    if (t < N_SCAN_BLOCKS) boff[t] = s[t] - v;
    if (t == N_SCAN_BLOCKS - 1) rowptr[N_NODES] = s[t];
}

__global__ __launch_bounds__(SCAN_BS) void k_scanapply(const int* __restrict__ deg,
                                                       const int* __restrict__ boff,
                                                       int* __restrict__ rowptr,
                                                       int* __restrict__ cursor) {
    __shared__ int s[SCAN_BS];
    int b = blockIdx.x, t = threadIdx.x;
    int i = b * SCAN_BS + t;
    int v = (i < N_NODES) ? pad4(deg[i]) : 0;
    s[t] = v;
    __syncthreads();
    for (int off = 1; off < SCAN_BS; off <<= 1) {
        int u = (t >= off) ? s[t - off] : 0;
        __syncthreads();
        s[t] += u;
        __syncthreads();
    }
    if (i < N_NODES) {
        int excl = boff[b] + s[t] - v;
        rowptr[i] = excl;
        cursor[i] = excl;
    }
}

__global__ void k_fill(const int* __restrict__ ei, const float* __restrict__ dinv,
                       int* __restrict__ cursor, int* __restrict__ esrc,
                       float* __restrict__ enorm) {
    int e = blockIdx.x * blockDim.x + threadIdx.x;
    if (e >= N_EDGES) return;
    int r = ei[e];
    int c = ei[N_EDGES + e];
    int pos = atomicAdd(&cursor[c], 1);
    esrc[pos] = r;
    enorm[pos] = dinv[r] * dinv[c];
}

// ---------------- GEMM common (fp16 A, fp16 hi/lo W; 2-term) ----------------
#define OFF_A  0u
#define OFF_WH 16384u
#define OFF_WL 49152u
#define GEMM_SMEM 81920
#define GEMM_TPB 256

__device__ __forceinline__ uint2 half_pack4(float4 v) {
    __half2 p0 = __floats2half2_rn(v.x, v.y);
    __half2 p1 = __floats2half2_rn(v.z, v.w);
    return make_uint2(*(uint32_t*)&p0, *(uint32_t*)&p1);
}

__device__ __forceinline__ void w_copy_async(uint32_t sb, int tid, int layer) {
    const unsigned char* sh = g_wt + (size_t)(layer * 2 + 0) * 32768;
    const unsigned char* sl = g_wt + (size_t)(layer * 2 + 1) * 32768;
#pragma unroll
    for (int j = 0; j < 8; j++) {
        uint32_t off = (uint32_t)(tid + j * 256) * 16;
        CP_ASYNC16(sb + OFF_WH + off, sh + off);
        CP_ASYNC16(sb + OFF_WL + off, sl + off);
    }
}

// shared mainloop + fp16 epilogue
__device__ __forceinline__ void mma_main_epi(uint32_t sb, int tid, int row0,
                                             __half* __restrict__ H) {
    const int w = tid >> 5;
    const int lane = tid & 31;
    const int wm = w >> 2;
    const int wn = w & 3;

    float acc[2][4][4];
#pragma unroll
    for (int mi = 0; mi < 2; mi++)
#pragma unroll
        for (int ni = 0; ni < 4; ni++)
#pragma unroll
            for (int j = 0; j < 4; j++) acc[mi][ni][j] = 0.f;

    const int a_row = wm * 32 + (lane & 15);
    const int a_kb  = (lane >> 4) << 4;
    const int b_row = wn * 32 + ((lane >> 4) << 3) + (lane & 7);
    const int b_kb  = ((lane >> 3) & 1) << 4;

#pragma unroll
    for (int ks = 0; ks < 8; ks++) {
        uint32_t av[2][4], bh[2][4], bl[2][4];
#pragma unroll
        for (int mi = 0; mi < 2; mi++) {
            uint32_t addr = swz(a_row + mi * 16, a_kb + ks * 32);
            LDSM_X4(av[mi], sb + OFF_A + addr);
        }
#pragma unroll
        for (int p = 0; p < 2; p++) {
            uint32_t addr = swz(b_row + p * 16, b_kb + ks * 32);
            LDSM_X4(bh[p], sb + OFF_WH + addr);
            LDSM_X4(bl[p], sb + OFF_WL + addr);
        }
#pragma unroll
        for (int mi = 0; mi < 2; mi++) {
#pragma unroll
            for (int p = 0; p < 2; p++) {
#pragma unroll
                for (int s = 0; s < 2; s++) {
                    int ni = p * 2 + s;
                    MMA_F16(acc[mi][ni], av[mi], bh[p][s * 2], bh[p][s * 2 + 1]);
                    MMA_F16(acc[mi][ni], av[mi], bl[p][s * 2], bl[p][s * 2 + 1]);
                }
            }
        }
    }

#pragma unroll
    for (int mi = 0; mi < 2; mi++) {
        int r1 = row0 + wm * 32 + mi * 16 + (lane >> 2);
        int r2 = r1 + 8;
#pragma unroll
        for (int ni = 0; ni < 4; ni++) {
            int col = wn * 32 + ni * 8 + 2 * (lane & 3);
            if (r1 < N_NODES)
                *(__half2*)(H + (size_t)r1 * D + col) =
                    __floats2half2_rn(acc[mi][ni][0], acc[mi][ni][1]);
            if (r2 < N_NODES)
                *(__half2*)(H + (size_t)r2 * D + col) =
                    __floats2half2_rn(acc[mi][ni][2], acc[mi][ni][3]);
        }
    }
}

// ---------------- dense GEMM (layer 0): inline X->fp16 staging ----------------
__global__ __launch_bounds__(GEMM_TPB, 2) void k_gemm_d(const float* __restrict__ X,
                                                        __half* __restrict__ H) {
    extern __shared__ unsigned char smem[];
    const uint32_t sb = s2u(smem);
    const int tid = threadIdx.x;
    const int row0 = blockIdx.x * M_TILE;

    w_copy_async(sb, tid, 0);
    CP_COMMIT();

    {
        int r = tid >> 2;
        int q = tid & 3;
        int gr = row0 + r;
        bool valid = gr < N_NODES;
        const float4* src = (const float4*)(X + (size_t)gr * D);
#pragma unroll
        for (int j = 0; j < 8; j++) {
            int qp = q + j * 4;
            float4 v = valid ? src[qp] : make_float4(0.f, 0.f, 0.f, 0.f);
            uint2 u = half_pack4(v);
            *(uint2*)(smem + OFF_A + swz(r, qp * 8)) = u;
        }
    }
    CP_WAIT0();
    __syncthreads();
    mma_main_epi(sb, tid, row0, H);
}

// ---------------- pre-staged GEMM (layers 1,2) ----------------
__global__ __launch_bounds__(GEMM_TPB, 2) void k_gemm_ps(int layer,
                                                         __half* __restrict__ H) {
    extern __shared__ unsigned char smem[];
    const uint32_t sb = s2u(smem);
    const int tid = threadIdx.x;
    const int row0 = blockIdx.x * M_TILE;

    w_copy_async(sb, tid, layer);
    {
        const unsigned char* ah = g_ahi + (size_t)blockIdx.x * 16384;
#pragma unroll
        for (int j = 0; j < 4; j++) {
            uint32_t off = (uint32_t)(tid + j * 256) * 16;
            CP_ASYNC16(sb + OFF_A + off, ah + off);
        }
    }
    CP_COMMIT();
    CP_WAIT0();
    __syncthreads();
    mma_main_epi(sb, tid, row0, H);
}

// ---------------- quad-node gather (4 nodes/warp, MLP=16, pad4) ----------------
// SPLIT=true: fused bias+relu, quantize to fp16, write swizzled A image.
// SPLIT=false: bias only, write fp32 rows to out.
template <bool SPLIT>
__global__ __launch_bounds__(256) void k_gather(const int* __restrict__ rowptr,
                                                const int* __restrict__ esrc,
                                                const float* __restrict__ enorm,
                                                const __half* __restrict__ H,
                                                const float* __restrict__ bvec,
                                                float* __restrict__ out) {
    int base = blockIdx.x * 32 + (threadIdx.x >> 5) * 4;
    if (base >= N_NODES) return;
    int lane = threadIdx.x & 31;

    float4 bv = ((const float4*)bvec)[lane];
    float4 acc[4];
    int e[4], end[4];
#pragma unroll
    for (int q = 0; q < 4; q++) {
        acc[q] = bv;
        int n = base + q;
        bool has = n < N_NODES;
        e[q] = has ? rowptr[n] : 0;
        end[q] = has ? rowptr[n + 1] : 0;
    }

    const float4 fz = make_float4(0.f, 0.f, 0.f, 0.f);

    while (e[0] < end[0] || e[1] < end[1] || e[2] < end[2] || e[3] < end[3]) {
        int4 s4[4];
        float4 nn[4];
#pragma unroll
        for (int q = 0; q < 4; q++) {
            bool a = e[q] < end[q];
            int ee = a ? e[q] : 0;
            s4[q] = __ldg((const int4*)(esrc + ee));
            nn[q] = a ? __ldg((const float4*)(enorm + ee)) : fz;
        }
        // 16 independent row loads in flight
        uint2 r[4][4];
#pragma unroll
        for (int q = 0; q < 4; q++) {
            r[q][0] = __ldg((const uint2*)(H + (size_t)s4[q].x * D) + lane);
            r[q][1] = __ldg((const uint2*)(H + (size_t)s4[q].y * D) + lane);
            r[q][2] = __ldg((const uint2*)(H + (size_t)s4[q].z * D) + lane);
            r[q][3] = __ldg((const uint2*)(H + (size_t)s4[q].w * D) + lane);
        }
#pragma unroll
        for (int q = 0; q < 4; q++) {
            const float nv[4] = {nn[q].x, nn[q].y, nn[q].z, nn[q].w};
#pragma unroll
            for (int j = 0; j < 4; j++) {
                float2 f0 = __half22float2(*(__half2*)&r[q][j].x);
                float2 f1 = __half22float2(*(__half2*)&r[q][j].y);
                acc[q].x += f0.x * nv[j]; acc[q].y += f0.y * nv[j];
                acc[q].z += f1.x * nv[j]; acc[q].w += f1.y * nv[j];
            }
            if (e[q] < end[q]) e[q] += 4;
        }
    }

#pragma unroll
    for (int q = 0; q < 4; q++) {
        int n = base + q;
        if (n >= N_NODES) break;
        float4 a = acc[q];
        if (SPLIT) {
            a.x = fmaxf(a.x, 0.f); a.y = fmaxf(a.y, 0.f);
            a.z = fmaxf(a.z, 0.f); a.w = fmaxf(a.w, 0.f);
            uint2 u = half_pack4(a);
            size_t bo = (size_t)(n >> 6) * 16384 + swz(n & 63, lane * 8);
            *(uint2*)(g_ahi + bo) = u;
        } else {
            ((float4*)(out + (size_t)n * D))[lane] = a;
        }
    }
}

// ---------------- launch ----------------
extern "C" void kernel_launch(void* const* d_in, const int* in_sizes, int n_in,
                              void* d_out, int out_size) {
    const float* x = (const float*)d_in[0];
    const int* ei_raw = (const int*)d_in[1];
    const float* W = (const float*)d_in[3];
    const float* b = (const float*)d_in[4];
    float* out = (float*)d_out;

    float *dinv, *enorm;
    __half *h, *h2;
    int *deg, *rowptr, *cursor, *bsum, *boff, *esrc, *ei;
    cudaGetSymbolAddress((void**)&dinv, g_dinv);
    cudaGetSymbolAddress((void**)&h, g_h);
    cudaGetSymbolAddress((void**)&h2, g_h2);
    cudaGetSymbolAddress((void**)&enorm, g_enorm);
    cudaGetSymbolAddress((void**)&deg, g_deg);
    cudaGetSymbolAddress((void**)&rowptr, g_rowptr);
    cudaGetSymbolAddress((void**)&cursor, g_cursor);
    cudaGetSymbolAddress((void**)&bsum, g_bsum);
    cudaGetSymbolAddress((void**)&boff, g_boff);
    cudaGetSymbolAddress((void**)&esrc, g_esrc);
    cudaGetSymbolAddress((void**)&ei, g_ei);

    cudaFuncSetAttribute(k_gemm_d, cudaFuncAttributeMaxDynamicSharedMemorySize, GEMM_SMEM);
    cudaFuncSetAttribute(k_gemm_ps, cudaFuncAttributeMaxDynamicSharedMemorySize, GEMM_SMEM);

    const int TPB = 256;
    const int GATH_BLOCKS = (N_NODES + 31) / 32;   // 4 nodes/warp, 8 warps/block

    // fork: wprep + dense gemm0 overlap the edge-prep chain
    cudaStream_t s2;
    cudaEvent_t evFork, evJoin;
    cudaStreamCreateWithFlags(&s2, cudaStreamNonBlocking);
    cudaEventCreateWithFlags(&evFork, cudaEventDisableTiming);
    cudaEventCreateWithFlags(&evJoin, cudaEventDisableTiming);

    cudaEventRecord(evFork, 0);
    cudaStreamWaitEvent(s2, evFork, 0);

    k_wprep<<<(3 * 128 * 128 + TPB - 1) / TPB, TPB, 0, s2>>>(W);
    k_gemm_d<<<GEMM_BLOCKS, GEMM_TPB, GEMM_SMEM, s2>>>(x, h);
    cudaEventRecord(evJoin, s2);

    // main: edge-prep chain (padded CSR, pad4)
    cudaMemsetAsync(deg, 0, N_NODES * sizeof(int), 0);
    cudaMemsetAsync(esrc, 0, E_PAD * sizeof(int), 0);
    cudaMemsetAsync(enorm, 0, E_PAD * sizeof(float), 0);
    k_convert_hist<<<(N_EDGES + TPB - 1) / TPB, TPB>>>(ei_raw, ei, deg);
    k_dinv_bsum<<<N_SCAN_BLOCKS, 256>>>(deg, dinv, bsum);
    k_scansums<<<1, 128>>>(bsum, boff, rowptr);
    k_scanapply<<<N_SCAN_BLOCKS, SCAN_BS>>>(deg, boff, rowptr, cursor);
    k_fill<<<(N_EDGES + TPB - 1) / TPB, TPB>>>(ei, dinv, cursor, esrc, enorm);

    cudaStreamWaitEvent(0, evJoin, 0);

    // layer 1: gather(h)+b0+relu -> fp16 A image; GEMM W1 -> h2
    k_gather<true><<<GATH_BLOCKS, TPB>>>(rowptr, esrc, enorm, h, b + 0 * D, nullptr);
    k_gemm_ps<<<GEMM_BLOCKS, GEMM_TPB, GEMM_SMEM>>>(1, h2);
    // layer 2: gather(h2)+b1+relu -> fp16 A image; GEMM W2 -> h
    k_gather<true><<<GATH_BLOCKS, TPB>>>(rowptr, esrc, enorm, h2, b + 1 * D, nullptr);
    k_gemm_ps<<<GEMM_BLOCKS, GEMM_TPB, GEMM_SMEM>>>(2, h);
    // final: gather(h)+b2 -> out (fp32)
    k_gather<false><<<GATH_BLOCKS, TPB>>>(rowptr, esrc, enorm, h, b + 2 * D, out);
}

// round 17
// speedup vs baseline: 1.1375x; 1.1375x over previous
#include <cuda_runtime.h>
#include <cuda_fp16.h>
#include <cstdint>

#define N_NODES 100000
#define N_EDGES 640000
#define E_PAD 1048576   // >= sum of pad4(deg)
#define D 128
#define SCAN_BS 1024
#define N_SCAN_BLOCKS ((N_NODES + SCAN_BS - 1) / SCAN_BS)  // 98
#define M_TILE 64
#define GEMM_BLOCKS ((N_NODES + M_TILE - 1) / M_TILE)      // 1563

// ---- scratch ----
__device__ __half g_h[(size_t)N_NODES * D];
__device__ __half g_h2[(size_t)N_NODES * D];
// pre-swizzled fp16 A-tile images: [tile][64 rows][256B] = 16KB/tile
__device__ unsigned char g_ahi[(size_t)GEMM_BLOCKS * 16384];
__device__ int   g_deg[N_NODES];
__device__ float g_dinv[N_NODES];
__device__ int   g_rowptr[N_NODES + 1];
__device__ int   g_cursor[N_NODES];
__device__ int   g_bsum[128];
__device__ int   g_boff[128];
__device__ int   g_esrc[E_PAD];
__device__ float g_enorm[E_PAD];
__device__ int   g_ei[2 * N_EDGES];
// W transposed, fp16 hi/lo split, pre-swizzled: [layer][hi|lo] 32KB each
__device__ unsigned char g_wt[3 * 2 * 32768];

__device__ __forceinline__ uint32_t swz(int row, int kb) {
    return (uint32_t)(row * 256 + (kb ^ ((row & 7) << 4)));
}

__device__ __forceinline__ uint32_t s2u(const void* p) {
    uint32_t a;
    asm("{ .reg .u64 t; cvta.to.shared.u64 t, %1; cvt.u32.u64 %0, t; }"
        : "=r"(a) : "l"(p));
    return a;
}

#define LDSM_X4(d, a) \
    asm volatile("ldmatrix.sync.aligned.m8n8.x4.shared.b16 {%0,%1,%2,%3}, [%4];" \
        : "=r"((d)[0]), "=r"((d)[1]), "=r"((d)[2]), "=r"((d)[3]) : "r"(a))

#define MMA_F16(c, a, b0, b1) \
    asm volatile("mma.sync.aligned.m16n8k16.row.col.f32.f16.f16.f32 " \
        "{%0,%1,%2,%3}, {%4,%5,%6,%7}, {%8,%9}, {%0,%1,%2,%3};" \
        : "+f"((c)[0]), "+f"((c)[1]), "+f"((c)[2]), "+f"((c)[3]) \
        : "r"((a)[0]), "r"((a)[1]), "r"((a)[2]), "r"((a)[3]), "r"(b0), "r"(b1))

#define CP_ASYNC16(dst, src) \
    asm volatile("cp.async.ca.shared.global [%0], [%1], 16;" :: "r"(dst), "l"(src))
#define CP_COMMIT() asm volatile("cp.async.commit_group;")
#define CP_WAIT0()  asm volatile("cp.async.wait_group 0;")

__device__ __forceinline__ int pad4(int d) { return (d + 3) & ~3; }

// ---------------- edge-index dtype sniff ----------------
__device__ __forceinline__ bool ei_is_int64(const int* __restrict__ w) {
    bool z = true;
#pragma unroll
    for (int i = 1; i < 32; i += 2) z &= (w[i] == 0);
    return z;
}

__global__ void k_convert_hist(const int* __restrict__ ei_raw, int* __restrict__ ei32,
                               int* __restrict__ deg) {
    int e = blockIdx.x * blockDim.x + threadIdx.x;
    if (e >= N_EDGES) return;
    bool is64 = ei_is_int64(ei_raw);
    int r = is64 ? ei_raw[2 * e] : ei_raw[e];
    int c = is64 ? ei_raw[2 * (N_EDGES + e)] : ei_raw[N_EDGES + e];
    ei32[e] = r;
    ei32[N_EDGES + e] = c;
    atomicAdd(&deg[c], 1);
}

// ---------------- W prep: transpose + fp16 hi/lo split + swizzle ----------------
__global__ void k_wprep(const float* __restrict__ W) {
    int i = blockIdx.x * blockDim.x + threadIdx.x;
    if (i >= 3 * 128 * 128) return;
    int l = i >> 14;
    int rem = i & 16383;
    int k = rem >> 7;
    int n = rem & 127;
    float w = W[l * 16384 + k * 128 + n];
    __half hb = __float2half_rn(w);
    __half lb = __float2half_rn(w - __half2float(hb));
    uint32_t pos = swz(n, k * 2);
    *(__half*)(g_wt + (size_t)(l * 2 + 0) * 32768 + pos) = hb;
    *(__half*)(g_wt + (size_t)(l * 2 + 1) * 32768 + pos) = lb;
}

// ---------------- prep (padded CSR, pad4) ----------------
__global__ __launch_bounds__(256) void k_dinv_bsum(const int* __restrict__ deg,
                                                   float* __restrict__ dinv,
                                                   int* __restrict__ bsum) {
    __shared__ int s[256];
    int b = blockIdx.x, t = threadIdx.x;
    int base = b * SCAN_BS + t * 4;
    int v = 0;
#pragma unroll
    for (int j = 0; j < 4; j++) {
        int i = base + j;
        if (i < N_NODES) {
            int d = deg[i];
            dinv[i] = (d > 0) ? rsqrtf((float)d) : 0.f;
            v += pad4(d);
        }
    }
    s[t] = v;
    __syncthreads();
    for (int off = 128; off > 0; off >>= 1) {
        if (t < off) s[t] += s[t + off];
        __syncthreads();
    }
    if (t == 0) bsum[b] = s[0];
}

__global__ __launch_bounds__(128) void k_scansums(const int* __restrict__ bsum,
                                                  int* __restrict__ boff,
                                                  int* __restrict__ rowptr) {
    __shared__ int s[128];
    int t = threadIdx.x;
    int v = (t < N_SCAN_BLOCKS) ? bsum[t] : 0;
    s[t] = v;
    __syncthreads();
    for (int off = 1; off < 128; off <<= 1) {
        int u = (t >= off) ? s[t - off] : 0;
        __syncthreads();
        s[t] += u;
        __syncthreads();
    }
    if (t < N_SCAN_BLOCKS) boff[t] = s[t] - v;
    if (t == N_SCAN_BLOCKS - 1) rowptr[N_NODES] = s[t];
}

__global__ __launch_bounds__(SCAN_BS) void k_scanapply(const int* __restrict__ deg,
                                                       const int* __restrict__ boff,
                                                       int* __restrict__ rowptr,
                                                       int* __restrict__ cursor) {
    __shared__ int s[SCAN_BS];
    int b = blockIdx.x, t = threadIdx.x;
    int i = b * SCAN_BS + t;
    int v = (i < N_NODES) ? pad4(deg[i]) : 0;
    s[t] = v;
    __syncthreads();
    for (int off = 1; off < SCAN_BS; off <<= 1) {
        int u = (t >= off) ? s[t - off] : 0;
        __syncthreads();
        s[t] += u;
        __syncthreads();
    }
    if (i < N_NODES) {
        int excl = boff[b] + s[t] - v;
        rowptr[i] = excl;
        cursor[i] = excl;
    }
}

__global__ void k_fill(const int* __restrict__ ei, const float* __restrict__ dinv,
                       int* __restrict__ cursor, int* __restrict__ esrc,
                       float* __restrict__ enorm) {
    int e = blockIdx.x * blockDim.x + threadIdx.x;
    if (e >= N_EDGES) return;
    int r = ei[e];
    int c = ei[N_EDGES + e];
    int pos = atomicAdd(&cursor[c], 1);
    esrc[pos] = r;
    enorm[pos] = dinv[r] * dinv[c];
}

// ---------------- GEMM common ----------------
#define OFF_A  0u
#define OFF_WH 16384u
#define OFF_WL 49152u
#define GEMM_SMEM_D 81920     // layer 0: A + W_hi + W_lo (2-term, precise)
#define GEMM_SMEM_PS 49152    // layers 1,2: A + W_hi only (1-term, fast)
#define GEMM_TPB 256

__device__ __forceinline__ uint2 half_pack4(float4 v) {
    __half2 p0 = __floats2half2_rn(v.x, v.y);
    __half2 p1 = __floats2half2_rn(v.z, v.w);
    return make_uint2(*(uint32_t*)&p0, *(uint32_t*)&p1);
}

// shared mainloop + fp16 epilogue; TWO_TERM selects W_lo correction
template <bool TWO_TERM>
__device__ __forceinline__ void mma_main_epi(uint32_t sb, int tid, int row0,
                                             __half* __restrict__ H) {
    const int w = tid >> 5;
    const int lane = tid & 31;
    const int wm = w >> 2;
    const int wn = w & 3;

    float acc[2][4][4];
#pragma unroll
    for (int mi = 0; mi < 2; mi++)
#pragma unroll
        for (int ni = 0; ni < 4; ni++)
#pragma unroll
            for (int j = 0; j < 4; j++) acc[mi][ni][j] = 0.f;

    const int a_row = wm * 32 + (lane & 15);
    const int a_kb  = (lane >> 4) << 4;
    const int b_row = wn * 32 + ((lane >> 4) << 3) + (lane & 7);
    const int b_kb  = ((lane >> 3) & 1) << 4;

#pragma unroll
    for (int ks = 0; ks < 8; ks++) {
        uint32_t av[2][4], bh[2][4], bl[2][4];
#pragma unroll
        for (int mi = 0; mi < 2; mi++) {
            uint32_t addr = swz(a_row + mi * 16, a_kb + ks * 32);
            LDSM_X4(av[mi], sb + OFF_A + addr);
        }
#pragma unroll
        for (int p = 0; p < 2; p++) {
            uint32_t addr = swz(b_row + p * 16, b_kb + ks * 32);
            LDSM_X4(bh[p], sb + OFF_WH + addr);
            if (TWO_TERM) LDSM_X4(bl[p], sb + OFF_WL + addr);
        }
#pragma unroll
        for (int mi = 0; mi < 2; mi++) {
#pragma unroll
            for (int p = 0; p < 2; p++) {
#pragma unroll
                for (int s = 0; s < 2; s++) {
                    int ni = p * 2 + s;
                    MMA_F16(acc[mi][ni], av[mi], bh[p][s * 2], bh[p][s * 2 + 1]);
                    if (TWO_TERM)
                        MMA_F16(acc[mi][ni], av[mi], bl[p][s * 2], bl[p][s * 2 + 1]);
                }
            }
        }
    }

#pragma unroll
    for (int mi = 0; mi < 2; mi++) {
        int r1 = row0 + wm * 32 + mi * 16 + (lane >> 2);
        int r2 = r1 + 8;
#pragma unroll
        for (int ni = 0; ni < 4; ni++) {
            int col = wn * 32 + ni * 8 + 2 * (lane & 3);
            if (r1 < N_NODES)
                *(__half2*)(H + (size_t)r1 * D + col) =
                    __floats2half2_rn(acc[mi][ni][0], acc[mi][ni][1]);
            if (r2 < N_NODES)
                *(__half2*)(H + (size_t)r2 * D + col) =
                    __floats2half2_rn(acc[mi][ni][2], acc[mi][ni][3]);
        }
    }
}

// ---------------- dense GEMM (layer 0): inline X->fp16 staging, 2-term W ----------------
__global__ __launch_bounds__(GEMM_TPB, 2) void k_gemm_d(const float* __restrict__ X,
                                                        __half* __restrict__ H) {
    extern __shared__ unsigned char smem[];
    const uint32_t sb = s2u(smem);
    const int tid = threadIdx.x;
    const int row0 = blockIdx.x * M_TILE;

    {
        const unsigned char* sh = g_wt + (size_t)0 * 32768;
        const unsigned char* sl = g_wt + (size_t)1 * 32768;
#pragma unroll
        for (int j = 0; j < 8; j++) {
            uint32_t off = (uint32_t)(tid + j * 256) * 16;
            CP_ASYNC16(sb + OFF_WH + off, sh + off);
            CP_ASYNC16(sb + OFF_WL + off, sl + off);
        }
        CP_COMMIT();
    }

    {
        int r = tid >> 2;
        int q = tid & 3;
        int gr = row0 + r;
        bool valid = gr < N_NODES;
        const float4* src = (const float4*)(X + (size_t)gr * D);
#pragma unroll
        for (int j = 0; j < 8; j++) {
            int qp = q + j * 4;
            float4 v = valid ? src[qp] : make_float4(0.f, 0.f, 0.f, 0.f);
            uint2 u = half_pack4(v);
            *(uint2*)(smem + OFF_A + swz(r, qp * 8)) = u;
        }
    }
    CP_WAIT0();
    __syncthreads();
    mma_main_epi<true>(sb, tid, row0, H);
}

// ---------------- pre-staged GEMM (layers 1,2): 1-term fp16 W ----------------
__global__ __launch_bounds__(GEMM_TPB, 4) void k_gemm_ps(int layer,
                                                         __half* __restrict__ H) {
    extern __shared__ unsigned char smem[];
    const uint32_t sb = s2u(smem);
    const int tid = threadIdx.x;
    const int row0 = blockIdx.x * M_TILE;

    {
        const unsigned char* sh = g_wt + (size_t)(layer * 2 + 0) * 32768;
#pragma unroll
        for (int j = 0; j < 8; j++) {
            uint32_t off = (uint32_t)(tid + j * 256) * 16;
            CP_ASYNC16(sb + OFF_WH + off, sh + off);
        }
        const unsigned char* ah = g_ahi + (size_t)blockIdx.x * 16384;
#pragma unroll
        for (int j = 0; j < 4; j++) {
            uint32_t off = (uint32_t)(tid + j * 256) * 16;
            CP_ASYNC16(sb + OFF_A + off, ah + off);
        }
    }
    CP_COMMIT();
    CP_WAIT0();
    __syncthreads();
    mma_main_epi<false>(sb, tid, row0, H);
}

// ---------------- dual-node gather (2 nodes/warp, MLP=8, pad4) ----------------
// SPLIT=true: fused bias+relu, quantize to fp16, write swizzled A image.
// SPLIT=false: bias only, write fp32 rows to out.
template <bool SPLIT>
__global__ __launch_bounds__(256) void k_gather(const int* __restrict__ rowptr,
                                                const int* __restrict__ esrc,
                                                const float* __restrict__ enorm,
                                                const __half* __restrict__ H,
                                                const float* __restrict__ bvec,
                                                float* __restrict__ out) {
    int base = blockIdx.x * 16 + (threadIdx.x >> 5) * 2;
    if (base >= N_NODES) return;
    int lane = threadIdx.x & 31;
    int n0 = base;
    int n1 = base + 1;
    bool has1 = n1 < N_NODES;

    float4 bv = ((const float4*)bvec)[lane];
    float4 acc0 = bv, acc1 = bv;

    int e0 = rowptr[n0];
    int end0 = rowptr[n0 + 1];
    int e1 = has1 ? rowptr[n1] : 0;
    int end1 = has1 ? rowptr[n1 + 1] : 0;

    const float4 fz = make_float4(0.f, 0.f, 0.f, 0.f);

    while (e0 < end0 || e1 < end1) {          // warp-uniform condition
        bool a0 = e0 < end0, a1 = e1 < end1;
        int ea = a0 ? e0 : 0;
        int eb = a1 ? e1 : 0;
        int4 sa = __ldg((const int4*)(esrc + ea));
        int4 sb4 = __ldg((const int4*)(esrc + eb));
        float4 na = a0 ? __ldg((const float4*)(enorm + ea)) : fz;
        float4 nb = a1 ? __ldg((const float4*)(enorm + eb)) : fz;

        // 8 independent row loads in flight
        uint2 r0 = __ldg((const uint2*)(H + (size_t)sa.x * D) + lane);
        uint2 r1 = __ldg((const uint2*)(H + (size_t)sa.y * D) + lane);
        uint2 r2 = __ldg((const uint2*)(H + (size_t)sa.z * D) + lane);
        uint2 r3 = __ldg((const uint2*)(H + (size_t)sa.w * D) + lane);
        uint2 r4 = __ldg((const uint2*)(H + (size_t)sb4.x * D) + lane);
        uint2 r5 = __ldg((const uint2*)(H + (size_t)sb4.y * D) + lane);
        uint2 r6 = __ldg((const uint2*)(H + (size_t)sb4.z * D) + lane);
        uint2 r7 = __ldg((const uint2*)(H + (size_t)sb4.w * D) + lane);

#define ACCV(accv, raw, nv) do { \
        float2 f0 = __half22float2(*(__half2*)&(raw).x); \
        float2 f1 = __half22float2(*(__half2*)&(raw).y); \
        (accv).x += f0.x * (nv); (accv).y += f0.y * (nv); \
        (accv).z += f1.x * (nv); (accv).w += f1.y * (nv); } while (0)
        ACCV(acc0, r0, na.x); ACCV(acc0, r1, na.y);
        ACCV(acc0, r2, na.z); ACCV(acc0, r3, na.w);
        ACCV(acc1, r4, nb.x); ACCV(acc1, r5, nb.y);
        ACCV(acc1, r6, nb.z); ACCV(acc1, r7, nb.w);
#undef ACCV
        if (a0) e0 += 4;
        if (a1) e1 += 4;
    }

    if (SPLIT) {
        acc0.x = fmaxf(acc0.x, 0.f); acc0.y = fmaxf(acc0.y, 0.f);
        acc0.z = fmaxf(acc0.z, 0.f); acc0.w = fmaxf(acc0.w, 0.f);
        uint2 u0 = half_pack4(acc0);
        size_t b0 = (size_t)(n0 >> 6) * 16384 + swz(n0 & 63, lane * 8);
        *(uint2*)(g_ahi + b0) = u0;
        if (has1) {
            acc1.x = fmaxf(acc1.x, 0.f); acc1.y = fmaxf(acc1.y, 0.f);
            acc1.z = fmaxf(acc1.z, 0.f); acc1.w = fmaxf(acc1.w, 0.f);
            uint2 u1 = half_pack4(acc1);
            size_t b1 = (size_t)(n1 >> 6) * 16384 + swz(n1 & 63, lane * 8);
            *(uint2*)(g_ahi + b1) = u1;
        }
    } else {
        ((float4*)(out + (size_t)n0 * D))[lane] = acc0;
        if (has1)
            ((float4*)(out + (size_t)n1 * D))[lane] = acc1;
    }
}

// ---------------- launch ----------------
extern "C" void kernel_launch(void* const* d_in, const int* in_sizes, int n_in,
                              void* d_out, int out_size) {
    const float* x = (const float*)d_in[0];
    const int* ei_raw = (const int*)d_in[1];
    const float* W = (const float*)d_in[3];
    const float* b = (const float*)d_in[4];
    float* out = (float*)d_out;

    float *dinv, *enorm;
    __half *h, *h2;
    int *deg, *rowptr, *cursor, *bsum, *boff, *esrc, *ei;
    cudaGetSymbolAddress((void**)&dinv, g_dinv);
    cudaGetSymbolAddress((void**)&h, g_h);
    cudaGetSymbolAddress((void**)&h2, g_h2);
    cudaGetSymbolAddress((void**)&enorm, g_enorm);
    cudaGetSymbolAddress((void**)&deg, g_deg);
    cudaGetSymbolAddress((void**)&rowptr, g_rowptr);
    cudaGetSymbolAddress((void**)&cursor, g_cursor);
    cudaGetSymbolAddress((void**)&bsum, g_bsum);
    cudaGetSymbolAddress((void**)&boff, g_boff);
    cudaGetSymbolAddress((void**)&esrc, g_esrc);
    cudaGetSymbolAddress((void**)&ei, g_ei);

    cudaFuncSetAttribute(k_gemm_d, cudaFuncAttributeMaxDynamicSharedMemorySize, GEMM_SMEM_D);
    cudaFuncSetAttribute(k_gemm_ps, cudaFuncAttributeMaxDynamicSharedMemorySize, GEMM_SMEM_PS);

    const int TPB = 256;
    const int GATH_BLOCKS = (N_NODES + 15) / 16;   // 2 nodes/warp, 8 warps/block

    // fork: wprep + dense gemm0 overlap the edge-prep chain
    cudaStream_t s2;
    cudaEvent_t evFork, evJoin;
    cudaStreamCreateWithFlags(&s2, cudaStreamNonBlocking);
    cudaEventCreateWithFlags(&evFork, cudaEventDisableTiming);
    cudaEventCreateWithFlags(&evJoin, cudaEventDisableTiming);

    cudaEventRecord(evFork, 0);
    cudaStreamWaitEvent(s2, evFork, 0);

    k_wprep<<<(3 * 128 * 128 + TPB - 1) / TPB, TPB, 0, s2>>>(W);
    k_gemm_d<<<GEMM_BLOCKS, GEMM_TPB, GEMM_SMEM_D, s2>>>(x, h);
    cudaEventRecord(evJoin, s2);

    // main: edge-prep chain (padded CSR, pad4)
    cudaMemsetAsync(deg, 0, N_NODES * sizeof(int), 0);
    cudaMemsetAsync(esrc, 0, E_PAD * sizeof(int), 0);
    cudaMemsetAsync(enorm, 0, E_PAD * sizeof(float), 0);
    k_convert_hist<<<(N_EDGES + TPB - 1) / TPB, TPB>>>(ei_raw, ei, deg);
    k_dinv_bsum<<<N_SCAN_BLOCKS, 256>>>(deg, dinv, bsum);
    k_scansums<<<1, 128>>>(bsum, boff, rowptr);
    k_scanapply<<<N_SCAN_BLOCKS, SCAN_BS>>>(deg, boff, rowptr, cursor);
    k_fill<<<(N_EDGES + TPB - 1) / TPB, TPB>>>(ei, dinv, cursor, esrc, enorm);

    cudaStreamWaitEvent(0, evJoin, 0);

    // layer 1: gather(h)+b0+relu -> fp16 A image; GEMM W1 -> h2
    k_gather<true><<<GATH_BLOCKS, TPB>>>(rowptr, esrc, enorm, h, b + 0 * D, nullptr);
    k_gemm_ps<<<GEMM_BLOCKS, GEMM_TPB, GEMM_SMEM_PS>>>(1, h2);
    // layer 2: gather(h2)+b1+relu -> fp16 A image; GEMM W2 -> h
    k_gather<true><<<GATH_BLOCKS, TPB>>>(rowptr, esrc, enorm, h2, b + 1 * D, nullptr);
    k_gemm_ps<<<GEMM_BLOCKS, GEMM_TPB, GEMM_SMEM_PS>>>(2, h);
    // final: gather(h)+b2 -> out (fp32)
    k_gather<false><<<GATH_BLOCKS, TPB>>>(rowptr, esrc, enorm, h, b + 2 * D, out);
}